// round 2
// baseline (speedup 1.0000x reference)
#include <cuda_runtime.h>
#include <math.h>

// Problem constants (fixed by the dataset)
#define MAXN      6144
#define D         512
#define D4        128          // D / 4 floats
#define INV_PI    0.318309886183790671f

// Scratch (allocation-free rule: __device__ globals)
__device__ int   g_prev[MAXN];
__device__ int   g_next[MAXN];
__device__ float g_wprev[MAXN];       // weight of edge (i, prev[i])
__device__ float g_x[MAXN * D];       // gathered features
__device__ int   g_q64;               // 1 if qmask buffer is int64
__device__ int   g_d64;               // 1 if dia_len buffer is int64

// ---------------------------------------------------------------------------
// Kernel 0: dtype detection (deterministic; same inputs -> same flags).
// qmask is one-hot per node: in an int32 layout, q[2i] + q[2i+1] == 1 for all
// i. In an int64 layout (read as int32 words) that invariant breaks w.h.p.
// dia_len entries are positive; word 1 is zero iff the layout is int64.
// ---------------------------------------------------------------------------
__global__ void detect_kernel(const int* __restrict__ q,
                              const int* __restrict__ dl, int N)
{
    __shared__ int viol;
    if (threadIdx.x == 0) viol = 0;
    __syncthreads();
    int bad = 0;
    for (int i = threadIdx.x; i < N; i += blockDim.x) {
        if (q[2 * i] + q[2 * i + 1] != 1) bad = 1;
    }
    if (bad) atomicExch(&viol, 1);
    __syncthreads();
    if (threadIdx.x == 0) {
        g_q64 = viol;                    // invariant broken -> int64 layout
        g_d64 = (dl[1] == 0) ? 1 : 0;    // high word of first int64 entry
    }
}

// ---------------------------------------------------------------------------
// Kernel A: per-dialog edge discovery + edge weights.
// One block per dialog. Speaker flags staged through SMEM (coalesced), then
// thread 0 builds prev/next same-speaker chains; warps compute edge weights
// w = 1 - acos(clip(cos))/pi with a fused dot/norm pass.
// ---------------------------------------------------------------------------
__global__ void edge_kernel(const float* __restrict__ inputs,
                            const int* __restrict__ dl,
                            const int* __restrict__ q,
                            int n_dialogs)
{
    __shared__ int s_edge[512];   // nodes i with prev[i] >= 0
    __shared__ int s_sp[512];     // speaker flag per node in this dialog
    __shared__ int s_ne, s_start, s_len;

    int d = blockIdx.x;
    if (d >= n_dialogs) return;

    int dstride = g_d64 ? 2 : 1;
    int qstride = g_q64 ? 4 : 2;

    if (threadIdx.x == 0) {
        int start = 0;
        for (int t = 0; t < d; ++t) start += dl[t * dstride];
        s_start = start;
        s_len   = dl[d * dstride];
    }
    __syncthreads();

    int start = s_start, len = s_len;

    // coalesced speaker-flag load
    for (int t = threadIdx.x; t < len; t += blockDim.x)
        s_sp[t] = (q[(size_t)(start + t) * qstride] == 1) ? 0 : 1;
    __syncthreads();

    if (threadIdx.x == 0) {
        int last[2] = {-1, -1};
        int ne = 0;
        for (int t = 0; t < len; ++t) {
            int i = start + t;
            int s = s_sp[t];
            g_next[i] = -1;
            if (last[s] >= 0) {
                g_prev[i]       = last[s];
                g_next[last[s]] = i;
                s_edge[ne++]    = i;
            } else {
                g_prev[i] = -1;
            }
            last[s] = i;
        }
        s_ne = ne;
    }
    __syncthreads();

    int ne     = s_ne;
    int warp   = threadIdx.x >> 5;
    int lane   = threadIdx.x & 31;
    int nwarps = blockDim.x >> 5;

    for (int e = warp; e < ne; e += nwarps) {
        int i = s_edge[e];
        int p = g_prev[i];
        const float4* a4 = (const float4*)(inputs + (size_t)i * D);
        const float4* b4 = (const float4*)(inputs + (size_t)p * D);
        float dot = 0.f, na = 0.f, nb = 0.f;
        #pragma unroll
        for (int j = lane; j < D4; j += 32) {
            float4 a = a4[j];
            float4 b = b4[j];
            dot += a.x * b.x + a.y * b.y + a.z * b.z + a.w * b.w;
            na  += a.x * a.x + a.y * a.y + a.z * a.z + a.w * a.w;
            nb  += b.x * b.x + b.y * b.y + b.z * b.z + b.w * b.w;
        }
        #pragma unroll
        for (int off = 16; off > 0; off >>= 1) {
            dot += __shfl_down_sync(0xffffffffu, dot, off);
            na  += __shfl_down_sync(0xffffffffu, na,  off);
            nb  += __shfl_down_sync(0xffffffffu, nb,  off);
        }
        if (lane == 0) {
            float denom = sqrtf(na) * sqrtf(nb);
            float c = (denom > 0.f) ? (dot / denom) : 0.f;
            c = fminf(1.f, fmaxf(-1.f, c));
            g_wprev[i] = 1.f - acosf(c) * INV_PI;
        }
    }
}

// ---------------------------------------------------------------------------
// Kernel B: gather  x[i] = in[i] + w(i,prev)*in[prev] + w(i,next)*in[next]
// ---------------------------------------------------------------------------
__global__ void gather_kernel(const float* __restrict__ inputs, int N)
{
    int i = blockIdx.x;
    if (i >= N) return;
    int t = threadIdx.x;

    const float4* in4 = (const float4*)inputs;
    float4* x4 = (float4*)g_x;

    float4 v = in4[(size_t)i * D4 + t];
    int p  = g_prev[i];
    int nx = g_next[i];
    if (p >= 0) {
        float w = g_wprev[i];
        float4 u = in4[(size_t)p * D4 + t];
        v.x += w * u.x; v.y += w * u.y; v.z += w * u.z; v.w += w * u.w;
    }
    if (nx >= 0) {
        float w = g_wprev[nx];   // symmetric weight
        float4 u = in4[(size_t)nx * D4 + t];
        v.x += w * u.x; v.y += w * u.y; v.z += w * u.z; v.w += w * u.w;
    }
    x4[(size_t)i * D4 + t] = v;
}

// ---------------------------------------------------------------------------
// Kernel C: SGEMM  out[N, D] = x[N, D] @ W^T + b      (W is [D_OUT, D_IN])
// NT GEMM, 64x64 tile, K-tile 16, 256 threads, 4x4 per-thread micro-tile.
// ---------------------------------------------------------------------------
__global__ __launch_bounds__(256)
void gemm_kernel(const float* __restrict__ Wm,
                 const float* __restrict__ bias,
                 float* __restrict__ out, int N)
{
    __shared__ float As[16][64];
    __shared__ float Bs[16][64];

    int tid = threadIdx.x;
    int n0 = blockIdx.y * 64;   // rows (nodes)
    int m0 = blockIdx.x * 64;   // cols (output features)
    int tx = tid & 15;
    int ty = tid >> 4;

    float acc[4][4] = {};

    for (int k0 = 0; k0 < D; k0 += 16) {
        #pragma unroll
        for (int i = 0; i < 4; ++i) {
            int idx = tid + i * 256;
            int r = idx >> 4;
            int k = idx & 15;
            int n = n0 + r;
            As[k][r] = (n < N) ? g_x[(size_t)n * D + k0 + k] : 0.f;
            Bs[k][r] = Wm[(size_t)(m0 + r) * D + k0 + k];
        }
        __syncthreads();

        #pragma unroll
        for (int k = 0; k < 16; ++k) {
            float4 a = *(const float4*)&As[k][ty * 4];
            float4 b = *(const float4*)&Bs[k][tx * 4];
            acc[0][0] += a.x * b.x; acc[0][1] += a.x * b.y; acc[0][2] += a.x * b.z; acc[0][3] += a.x * b.w;
            acc[1][0] += a.y * b.x; acc[1][1] += a.y * b.y; acc[1][2] += a.y * b.z; acc[1][3] += a.y * b.w;
            acc[2][0] += a.z * b.x; acc[2][1] += a.z * b.y; acc[2][2] += a.z * b.z; acc[2][3] += a.z * b.w;
            acc[3][0] += a.w * b.x; acc[3][1] += a.w * b.y; acc[3][2] += a.w * b.z; acc[3][3] += a.w * b.w;
        }
        __syncthreads();
    }

    #pragma unroll
    for (int ii = 0; ii < 4; ++ii) {
        int row = n0 + ty * 4 + ii;
        if (row >= N) continue;
        #pragma unroll
        for (int jj = 0; jj < 4; ++jj) {
            int col = m0 + tx * 4 + jj;
            out[(size_t)row * D + col] = acc[ii][jj] + bias[col];
        }
    }
}

// ---------------------------------------------------------------------------
extern "C" void kernel_launch(void* const* d_in, const int* in_sizes, int n_in,
                              void* d_out, int out_size)
{
    const float* inputs  = (const float*)d_in[0];
    const int*   dia_len = (const int*)d_in[1];   // int32 or int64 (detected)
    const int*   qmask   = (const int*)d_in[2];   // int32 or int64 (detected)
    const float* Wm      = (const float*)d_in[3];
    const float* bias    = (const float*)d_in[4];
    float*       out     = (float*)d_out;

    int N  = in_sizes[0] / D;      // 6000
    int nd = 0;
    // number of dialogs: element count of dia_len under either dtype; we pass
    // an upper bound and let the prefix scan use only the first nd entries.
    // in_sizes[1] is the element count per metadata; dialogs have len 100 so
    // nd = N / 100 is exact for this dataset, but derive defensively:
    nd = in_sizes[1];
    if (nd > N) nd = N;
    // If metadata counted int32 words of an int64 buffer, nd is 2x too big;
    // edge_kernel strides correctly via g_d64, and blocks beyond the real
    // dialog count would read len 0 -> no work. To keep grid exact, clamp by
    // the known structure: total utterances N with at least 1 per dialog.

    detect_kernel<<<1, 256>>>(qmask, dia_len, N);
    edge_kernel<<<nd, 128>>>(inputs, dia_len, qmask, nd);
    gather_kernel<<<N, 128>>>(inputs, N);

    dim3 grid(D / 64, (N + 63) / 64);
    gemm_kernel<<<grid, 256>>>(Wm, bias, out, N);
}

// round 3
// speedup vs baseline: 1.5223x; 1.5223x over previous
#include <cuda_runtime.h>
#include <math.h>

// Problem constants (fixed by the dataset)
#define MAXN      6144
#define D         512
#define D4        128          // D / 4 floats
#define INV_PI    0.318309886183790671f

typedef unsigned long long ull;

// Scratch (allocation-free rule: __device__ globals)
__device__ int   g_prev[MAXN];
__device__ int   g_next[MAXN];
__device__ float g_wprev[MAXN];       // weight of edge (i, prev[i])
__device__ float g_x[MAXN * D];       // gathered features
__device__ int   g_q64;               // 1 if qmask buffer is int64
__device__ int   g_d64;               // 1 if dia_len buffer is int64

// ---- Blackwell packed f32x2 helpers (PTX-only; ptxas never auto-fuses) ----
__device__ __forceinline__ ull pack2(float x, float y) {
    ull r;
    asm("mov.b64 %0, {%1, %2};" : "=l"(r) : "f"(x), "f"(y));
    return r;
}
__device__ __forceinline__ void unpack2(ull v, float& x, float& y) {
    asm("mov.b64 {%0, %1}, %2;" : "=f"(x), "=f"(y) : "l"(v));
}
__device__ __forceinline__ void ffma2(ull& c, ull a, ull b) {
    asm("fma.rn.f32x2 %0, %1, %2, %0;" : "+l"(c) : "l"(a), "l"(b));
}

// ---------------------------------------------------------------------------
// Kernel 0: dtype detection (deterministic).
// qmask one-hot per node: int32 layout => q[2i]+q[2i+1]==1 for all i.
// dia_len positive: word 1 is 0 iff int64 layout.
// ---------------------------------------------------------------------------
__global__ void detect_kernel(const int* __restrict__ q,
                              const int* __restrict__ dl, int N)
{
    __shared__ int viol;
    if (threadIdx.x == 0) viol = 0;
    __syncthreads();
    int bad = 0;
    for (int i = threadIdx.x; i < N; i += blockDim.x)
        if (q[2 * i] + q[2 * i + 1] != 1) bad = 1;
    if (bad) atomicExch(&viol, 1);
    __syncthreads();
    if (threadIdx.x == 0) {
        g_q64 = viol;
        g_d64 = (dl[1] == 0) ? 1 : 0;
    }
}

// ---------------------------------------------------------------------------
// Kernel A: per-dialog edge discovery + edge weights. One block per dialog.
// ---------------------------------------------------------------------------
__global__ void edge_kernel(const float* __restrict__ inputs,
                            const int* __restrict__ dl,
                            const int* __restrict__ q,
                            int n_dialogs)
{
    __shared__ int s_edge[512];
    __shared__ int s_sp[512];
    __shared__ int s_ne, s_start, s_len;

    int d = blockIdx.x;
    if (d >= n_dialogs) return;

    int dstride = g_d64 ? 2 : 1;
    int qstride = g_q64 ? 4 : 2;

    if (threadIdx.x == 0) {
        int start = 0;
        for (int t = 0; t < d; ++t) start += dl[t * dstride];
        s_start = start;
        s_len   = dl[d * dstride];
    }
    __syncthreads();

    int start = s_start, len = s_len;

    for (int t = threadIdx.x; t < len; t += blockDim.x)
        s_sp[t] = (q[(size_t)(start + t) * qstride] == 1) ? 0 : 1;
    __syncthreads();

    if (threadIdx.x == 0) {
        int last[2] = {-1, -1};
        int ne = 0;
        for (int t = 0; t < len; ++t) {
            int i = start + t;
            int s = s_sp[t];
            g_next[i] = -1;
            if (last[s] >= 0) {
                g_prev[i]       = last[s];
                g_next[last[s]] = i;
                s_edge[ne++]    = i;
            } else {
                g_prev[i] = -1;
            }
            last[s] = i;
        }
        s_ne = ne;
    }
    __syncthreads();

    int ne     = s_ne;
    int warp   = threadIdx.x >> 5;
    int lane   = threadIdx.x & 31;
    int nwarps = blockDim.x >> 5;

    for (int e = warp; e < ne; e += nwarps) {
        int i = s_edge[e];
        int p = g_prev[i];
        const float4* a4 = (const float4*)(inputs + (size_t)i * D);
        const float4* b4 = (const float4*)(inputs + (size_t)p * D);
        float dot = 0.f, na = 0.f, nb = 0.f;
        #pragma unroll
        for (int j = lane; j < D4; j += 32) {
            float4 a = a4[j];
            float4 b = b4[j];
            dot += a.x * b.x + a.y * b.y + a.z * b.z + a.w * b.w;
            na  += a.x * a.x + a.y * a.y + a.z * a.z + a.w * a.w;
            nb  += b.x * b.x + b.y * b.y + b.z * b.z + b.w * b.w;
        }
        #pragma unroll
        for (int off = 16; off > 0; off >>= 1) {
            dot += __shfl_down_sync(0xffffffffu, dot, off);
            na  += __shfl_down_sync(0xffffffffu, na,  off);
            nb  += __shfl_down_sync(0xffffffffu, nb,  off);
        }
        if (lane == 0) {
            float denom = sqrtf(na) * sqrtf(nb);
            float c = (denom > 0.f) ? (dot / denom) : 0.f;
            c = fminf(1.f, fmaxf(-1.f, c));
            g_wprev[i] = 1.f - acosf(c) * INV_PI;
        }
    }
}

// ---------------------------------------------------------------------------
// Kernel B: gather  x[i] = in[i] + w(i,prev)*in[prev] + w(i,next)*in[next]
// ---------------------------------------------------------------------------
__global__ void gather_kernel(const float* __restrict__ inputs, int N)
{
    int i = blockIdx.x;
    if (i >= N) return;
    int t = threadIdx.x;

    const float4* in4 = (const float4*)inputs;
    float4* x4 = (float4*)g_x;

    float4 v = in4[(size_t)i * D4 + t];
    int p  = g_prev[i];
    int nx = g_next[i];
    if (p >= 0) {
        float w = g_wprev[i];
        float4 u = in4[(size_t)p * D4 + t];
        v.x += w * u.x; v.y += w * u.y; v.z += w * u.z; v.w += w * u.w;
    }
    if (nx >= 0) {
        float w = g_wprev[nx];
        float4 u = in4[(size_t)nx * D4 + t];
        v.x += w * u.x; v.y += w * u.y; v.z += w * u.z; v.w += w * u.w;
    }
    x4[(size_t)i * D4 + t] = v;
}

// ---------------------------------------------------------------------------
// Kernel C: SGEMM  out[N, 512] = x[N, 512] @ W^T + b     (W is [512, 512])
// 128x128 block tile, K-tile 16, 256 threads, 8x8 micro-tile per thread,
// double-buffered smem, packed fma.rn.f32x2 accumulation (2 FMA / issue).
// g_x is MAXN rows (6144): loads up to n0+127 <= 6015 are always in-bounds;
// rows >= N are never stored.
// ---------------------------------------------------------------------------
__global__ __launch_bounds__(256, 2)
void gemm_kernel(const float* __restrict__ Wm,
                 const float* __restrict__ bias,
                 float* __restrict__ out, int N)
{
    __shared__ float As[2][16][128];
    __shared__ float Bs[2][16][128];

    int tid = threadIdx.x;
    int n0 = blockIdx.y * 128;     // node rows
    int m0 = blockIdx.x * 128;     // output feature cols

    // -------- global load mapping: each thread loads 2 float4 per matrix
    int lr = tid & 127;            // row within the 128-tile
    int kg = (tid >> 7) * 8;       // k sub-offset: 0 or 8
    const float* gA = g_x + (size_t)(n0 + lr) * D + kg;
    const float* gB = Wm  + (size_t)(m0 + lr) * D + kg;

    // -------- compute mapping: 16x16 thread grid, 8x8 outputs each
    int tx = (tid & 15) * 8;       // col base
    int ty = (tid >> 4) * 8;       // row base

    ull acc[8][4];
    #pragma unroll
    for (int i = 0; i < 8; ++i)
        #pragma unroll
        for (int j = 0; j < 4; ++j) acc[i][j] = 0ull;

    // preload tile 0
    float4 sa0 = *(const float4*)(gA);
    float4 sa1 = *(const float4*)(gA + 4);
    float4 sb0 = *(const float4*)(gB);
    float4 sb1 = *(const float4*)(gB + 4);

    #pragma unroll
    for (;;) {
        As[0][kg + 0][lr] = sa0.x; As[0][kg + 1][lr] = sa0.y;
        As[0][kg + 2][lr] = sa0.z; As[0][kg + 3][lr] = sa0.w;
        As[0][kg + 4][lr] = sa1.x; As[0][kg + 5][lr] = sa1.y;
        As[0][kg + 6][lr] = sa1.z; As[0][kg + 7][lr] = sa1.w;
        Bs[0][kg + 0][lr] = sb0.x; Bs[0][kg + 1][lr] = sb0.y;
        Bs[0][kg + 2][lr] = sb0.z; Bs[0][kg + 3][lr] = sb0.w;
        Bs[0][kg + 4][lr] = sb1.x; Bs[0][kg + 5][lr] = sb1.y;
        Bs[0][kg + 6][lr] = sb1.z; Bs[0][kg + 7][lr] = sb1.w;
        break;
    }
    __syncthreads();

    int read = 0;
    #pragma unroll 1
    for (int kt = 0; kt < 32; ++kt) {
        if (kt < 31) {
            const float* pA = gA + (kt + 1) * 16;
            const float* pB = gB + (kt + 1) * 16;
            sa0 = *(const float4*)(pA);
            sa1 = *(const float4*)(pA + 4);
            sb0 = *(const float4*)(pB);
            sb1 = *(const float4*)(pB + 4);
        }

        #pragma unroll
        for (int k = 0; k < 16; ++k) {
            const float4* ap = (const float4*)&As[read][k][ty];
            float4 av0 = ap[0];
            float4 av1 = ap[1];
            const ull* bp = (const ull*)&Bs[read][k][tx];
            ull b0 = bp[0], b1 = bp[1], b2 = bp[2], b3 = bp[3];

            ull aa;
            aa = pack2(av0.x, av0.x);
            ffma2(acc[0][0], aa, b0); ffma2(acc[0][1], aa, b1);
            ffma2(acc[0][2], aa, b2); ffma2(acc[0][3], aa, b3);
            aa = pack2(av0.y, av0.y);
            ffma2(acc[1][0], aa, b0); ffma2(acc[1][1], aa, b1);
            ffma2(acc[1][2], aa, b2); ffma2(acc[1][3], aa, b3);
            aa = pack2(av0.z, av0.z);
            ffma2(acc[2][0], aa, b0); ffma2(acc[2][1], aa, b1);
            ffma2(acc[2][2], aa, b2); ffma2(acc[2][3], aa, b3);
            aa = pack2(av0.w, av0.w);
            ffma2(acc[3][0], aa, b0); ffma2(acc[3][1], aa, b1);
            ffma2(acc[3][2], aa, b2); ffma2(acc[3][3], aa, b3);
            aa = pack2(av1.x, av1.x);
            ffma2(acc[4][0], aa, b0); ffma2(acc[4][1], aa, b1);
            ffma2(acc[4][2], aa, b2); ffma2(acc[4][3], aa, b3);
            aa = pack2(av1.y, av1.y);
            ffma2(acc[5][0], aa, b0); ffma2(acc[5][1], aa, b1);
            ffma2(acc[5][2], aa, b2); ffma2(acc[5][3], aa, b3);
            aa = pack2(av1.z, av1.z);
            ffma2(acc[6][0], aa, b0); ffma2(acc[6][1], aa, b1);
            ffma2(acc[6][2], aa, b2); ffma2(acc[6][3], aa, b3);
            aa = pack2(av1.w, av1.w);
            ffma2(acc[7][0], aa, b0); ffma2(acc[7][1], aa, b1);
            ffma2(acc[7][2], aa, b2); ffma2(acc[7][3], aa, b3);
        }

        if (kt < 31) {
            int w = read ^ 1;
            As[w][kg + 0][lr] = sa0.x; As[w][kg + 1][lr] = sa0.y;
            As[w][kg + 2][lr] = sa0.z; As[w][kg + 3][lr] = sa0.w;
            As[w][kg + 4][lr] = sa1.x; As[w][kg + 5][lr] = sa1.y;
            As[w][kg + 6][lr] = sa1.z; As[w][kg + 7][lr] = sa1.w;
            Bs[w][kg + 0][lr] = sb0.x; Bs[w][kg + 1][lr] = sb0.y;
            Bs[w][kg + 2][lr] = sb0.z; Bs[w][kg + 3][lr] = sb0.w;
            Bs[w][kg + 4][lr] = sb1.x; Bs[w][kg + 5][lr] = sb1.y;
            Bs[w][kg + 6][lr] = sb1.z; Bs[w][kg + 7][lr] = sb1.w;
            __syncthreads();
            read ^= 1;
        }
    }

    // -------- epilogue: add bias, store float4 pairs
    float bv[8];
    #pragma unroll
    for (int j = 0; j < 8; ++j) bv[j] = bias[m0 + tx + j];

    #pragma unroll
    for (int i = 0; i < 8; ++i) {
        int row = n0 + ty + i;
        if (row >= N) continue;
        float o[8];
        #pragma unroll
        for (int j = 0; j < 4; ++j)
            unpack2(acc[i][j], o[2 * j], o[2 * j + 1]);
        #pragma unroll
        for (int j = 0; j < 8; ++j) o[j] += bv[j];
        float4* op = (float4*)(out + (size_t)row * D + m0 + tx);
        op[0] = make_float4(o[0], o[1], o[2], o[3]);
        op[1] = make_float4(o[4], o[5], o[6], o[7]);
    }
}

// ---------------------------------------------------------------------------
extern "C" void kernel_launch(void* const* d_in, const int* in_sizes, int n_in,
                              void* d_out, int out_size)
{
    const float* inputs  = (const float*)d_in[0];
    const int*   dia_len = (const int*)d_in[1];   // int32 or int64 (detected)
    const int*   qmask   = (const int*)d_in[2];   // int32 or int64 (detected)
    const float* Wm      = (const float*)d_in[3];
    const float* bias    = (const float*)d_in[4];
    float*       out     = (float*)d_out;

    int N  = in_sizes[0] / D;      // 6000
    int nd = in_sizes[1];
    if (nd > N) nd = N;

    detect_kernel<<<1, 256>>>(qmask, dia_len, N);
    edge_kernel<<<nd, 256>>>(inputs, dia_len, qmask, nd);
    gather_kernel<<<N, 128>>>(inputs, N);

    dim3 grid(D / 128, (N + 127) / 128);
    gemm_kernel<<<grid, 256>>>(Wm, bias, out, N);
}

// round 5
// speedup vs baseline: 1.6565x; 1.0882x over previous
#include <cuda_runtime.h>
#include <math.h>
#include <cstdint>

// Problem constants (fixed by the dataset)
#define MAXN      6144
#define D         512
#define D4        128
#define INV_PI    0.318309886183790671f

typedef unsigned long long ull;

// ---------------- device scratch (allocation-free rule) ----------------
__device__ int   g_prev[MAXN];
__device__ int   g_next[MAXN];
__device__ float g_wprev[MAXN];
__device__ float g_y[MAXN * D];       // Y = X @ W^T

// ---- Blackwell packed f32x2 helpers (base-family feature; compiles on sm_103) ----
__device__ __forceinline__ ull pack2(float x, float y) {
    ull r;
    asm("mov.b64 %0, {%1, %2};" : "=l"(r) : "f"(x), "f"(y));
    return r;
}
__device__ __forceinline__ void unpack2(ull v, float& x, float& y) {
    asm("mov.b64 {%0, %1}, %2;" : "=f"(x), "=f"(y) : "l"(v));
}
__device__ __forceinline__ void ffma2(ull& c, ull a, ull b) {
    asm("fma.rn.f32x2 %0, %1, %2, %0;" : "+l"(c) : "l"(a), "l"(b));
}

// ---------------------------------------------------------------------------
// Kernel 1: fused dtype-detect + per-dialog edge discovery + edge weights.
// One block per dialog; each block independently detects the int32/int64
// layout of qmask / dia_len (deterministic, read-only), then builds the
// same-speaker prev/next chains and cosine->acos edge weights.
// ---------------------------------------------------------------------------
__global__ void prep_kernel(const float* __restrict__ inputs,
                            const int* __restrict__ dl,
                            const int* __restrict__ q,
                            int n_dialogs, int N)
{
    __shared__ int s_edge[512];
    __shared__ int s_sp[512];
    __shared__ int s_ne, s_start, s_len;
    __shared__ int s_viol;

    int d = blockIdx.x;
    if (d >= n_dialogs) return;

    // --- dtype detection (local, redundant per block; all read-only) ---
    if (threadIdx.x == 0) s_viol = 0;
    __syncthreads();
    int bad = 0;
    for (int i = threadIdx.x; i < N; i += blockDim.x)
        if (q[2 * i] + q[2 * i + 1] != 1) bad = 1;   // holds iff int32 layout
    if (bad) atomicExch(&s_viol, 1);
    __syncthreads();
    int qstride = s_viol ? 4 : 2;          // int64 read as int32 words
    int dstride = (dl[1] == 0) ? 2 : 1;    // dia_len entries positive

    if (threadIdx.x == 0) {
        int start = 0;
        for (int t = 0; t < d; ++t) start += dl[t * dstride];
        s_start = start;
        s_len   = dl[d * dstride];
    }
    __syncthreads();

    int start = s_start, len = s_len;
    for (int t = threadIdx.x; t < len; t += blockDim.x)
        s_sp[t] = (q[(size_t)(start + t) * qstride] == 1) ? 0 : 1;
    __syncthreads();

    if (threadIdx.x == 0) {
        int last[2] = {-1, -1};
        int ne = 0;
        for (int t = 0; t < len; ++t) {
            int i = start + t;
            int s = s_sp[t];
            g_next[i] = -1;
            if (last[s] >= 0) {
                g_prev[i]       = last[s];
                g_next[last[s]] = i;
                s_edge[ne++]    = i;
            } else {
                g_prev[i] = -1;
            }
            last[s] = i;
        }
        s_ne = ne;
    }
    __syncthreads();

    int ne = s_ne, warp = threadIdx.x >> 5, lane = threadIdx.x & 31;
    int nwarps = blockDim.x >> 5;

    for (int e = warp; e < ne; e += nwarps) {
        int i = s_edge[e];
        int p = g_prev[i];
        const float4* a4 = (const float4*)(inputs + (size_t)i * D);
        const float4* b4 = (const float4*)(inputs + (size_t)p * D);
        float dot = 0.f, na = 0.f, nb = 0.f;
        #pragma unroll
        for (int j = lane; j < D4; j += 32) {
            float4 a = a4[j];
            float4 b = b4[j];
            dot += a.x * b.x + a.y * b.y + a.z * b.z + a.w * b.w;
            na  += a.x * a.x + a.y * a.y + a.z * a.z + a.w * a.w;
            nb  += b.x * b.x + b.y * b.y + b.z * b.z + b.w * b.w;
        }
        #pragma unroll
        for (int off = 16; off > 0; off >>= 1) {
            dot += __shfl_down_sync(0xffffffffu, dot, off);
            na  += __shfl_down_sync(0xffffffffu, na,  off);
            nb  += __shfl_down_sync(0xffffffffu, nb,  off);
        }
        if (lane == 0) {
            float denom = sqrtf(na) * sqrtf(nb);
            float c = (denom > 0.f) ? (dot / denom) : 0.f;
            c = fminf(1.f, fmaxf(-1.f, c));
            g_wprev[i] = 1.f - acosf(c) * INV_PI;
        }
    }
}

// ---------------------------------------------------------------------------
// Kernel 2: SGEMM  Y[N,512] = X[N,512] @ W^T        (W is [512,512] row-major)
// 128x64 block tile, K-tile 16, 128 threads, 8x8 micro-tile, double-buffered
// smem, packed fma.rn.f32x2 (2 FMA / fma-pipe issue).
// Grid = 47 x 8 = 376 CTAs, 4 CTAs/SM resident -> ~1.18x imbalance only.
// ---------------------------------------------------------------------------
__global__ __launch_bounds__(128, 4)
void gemm_kernel(const float* __restrict__ X,
                 const float* __restrict__ Wm,
                 int N)
{
    __shared__ float As[2][16][128];
    __shared__ float Bs[2][16][64];

    int tid = threadIdx.x;
    int m0 = blockIdx.x * 128;     // node rows
    int n0 = blockIdx.y * 64;      // output feature cols

    // ---- global load mapping ----
    int arow = m0 + tid;                       // one A row per thread
    if (arow >= N) arow = N - 1;               // clamp (rows >= N never stored)
    const float* gA = X + (size_t)arow * D;

    int bcol = tid & 63;
    int bk0  = (tid >> 6) * 8;                 // 0 or 8
    const float* gB = Wm + (size_t)(n0 + bcol) * D + bk0;

    // ---- compute mapping: 16x8 thread grid, 8x8 outputs each ----
    int tx = (tid & 7) * 8;        // col base within 64
    int ty = (tid >> 3) * 8;       // row base within 128

    ull acc[8][4];
    #pragma unroll
    for (int i = 0; i < 8; ++i)
        #pragma unroll
        for (int j = 0; j < 4; ++j) acc[i][j] = 0ull;

    float4 pa[4], pb[2];
    #pragma unroll
    for (int j = 0; j < 4; ++j) pa[j] = ((const float4*)gA)[j];
    #pragma unroll
    for (int j = 0; j < 2; ++j) pb[j] = ((const float4*)gB)[j];

    // stage buffer 0
    #pragma unroll
    for (int j = 0; j < 4; ++j) {
        As[0][j * 4 + 0][tid] = pa[j].x;
        As[0][j * 4 + 1][tid] = pa[j].y;
        As[0][j * 4 + 2][tid] = pa[j].z;
        As[0][j * 4 + 3][tid] = pa[j].w;
    }
    #pragma unroll
    for (int j = 0; j < 2; ++j) {
        Bs[0][bk0 + j * 4 + 0][bcol] = pb[j].x;
        Bs[0][bk0 + j * 4 + 1][bcol] = pb[j].y;
        Bs[0][bk0 + j * 4 + 2][bcol] = pb[j].z;
        Bs[0][bk0 + j * 4 + 3][bcol] = pb[j].w;
    }
    __syncthreads();

    #pragma unroll 1
    for (int kt = 0; kt < 32; ++kt) {
        int buf = kt & 1;
        if (kt < 31) {
            const float* nA = gA + (kt + 1) * 16;
            const float* nB = gB + (kt + 1) * 16;
            #pragma unroll
            for (int j = 0; j < 4; ++j) pa[j] = ((const float4*)nA)[j];
            #pragma unroll
            for (int j = 0; j < 2; ++j) pb[j] = ((const float4*)nB)[j];
        }

        #pragma unroll
        for (int k = 0; k < 16; ++k) {
            float4 av0 = *(const float4*)&As[buf][k][ty];
            float4 av1 = *(const float4*)&As[buf][k][ty + 4];
            const ull* bp = (const ull*)&Bs[buf][k][tx];
            ull b0 = bp[0], b1 = bp[1], b2 = bp[2], b3 = bp[3];

            ull aa;
            aa = pack2(av0.x, av0.x);
            ffma2(acc[0][0], aa, b0); ffma2(acc[0][1], aa, b1);
            ffma2(acc[0][2], aa, b2); ffma2(acc[0][3], aa, b3);
            aa = pack2(av0.y, av0.y);
            ffma2(acc[1][0], aa, b0); ffma2(acc[1][1], aa, b1);
            ffma2(acc[1][2], aa, b2); ffma2(acc[1][3], aa, b3);
            aa = pack2(av0.z, av0.z);
            ffma2(acc[2][0], aa, b0); ffma2(acc[2][1], aa, b1);
            ffma2(acc[2][2], aa, b2); ffma2(acc[2][3], aa, b3);
            aa = pack2(av0.w, av0.w);
            ffma2(acc[3][0], aa, b0); ffma2(acc[3][1], aa, b1);
            ffma2(acc[3][2], aa, b2); ffma2(acc[3][3], aa, b3);
            aa = pack2(av1.x, av1.x);
            ffma2(acc[4][0], aa, b0); ffma2(acc[4][1], aa, b1);
            ffma2(acc[4][2], aa, b2); ffma2(acc[4][3], aa, b3);
            aa = pack2(av1.y, av1.y);
            ffma2(acc[5][0], aa, b0); ffma2(acc[5][1], aa, b1);
            ffma2(acc[5][2], aa, b2); ffma2(acc[5][3], aa, b3);
            aa = pack2(av1.z, av1.z);
            ffma2(acc[6][0], aa, b0); ffma2(acc[6][1], aa, b1);
            ffma2(acc[6][2], aa, b2); ffma2(acc[6][3], aa, b3);
            aa = pack2(av1.w, av1.w);
            ffma2(acc[7][0], aa, b0); ffma2(acc[7][1], aa, b1);
            ffma2(acc[7][2], aa, b2); ffma2(acc[7][3], aa, b3);
        }

        if (kt < 31) {
            __syncthreads();              // all reads of `buf^1`'s prior contents done
            int w = buf ^ 1;
            #pragma unroll
            for (int j = 0; j < 4; ++j) {
                As[w][j * 4 + 0][tid] = pa[j].x;
                As[w][j * 4 + 1][tid] = pa[j].y;
                As[w][j * 4 + 2][tid] = pa[j].z;
                As[w][j * 4 + 3][tid] = pa[j].w;
            }
            #pragma unroll
            for (int j = 0; j < 2; ++j) {
                Bs[w][bk0 + j * 4 + 0][bcol] = pb[j].x;
                Bs[w][bk0 + j * 4 + 1][bcol] = pb[j].y;
                Bs[w][bk0 + j * 4 + 2][bcol] = pb[j].z;
                Bs[w][bk0 + j * 4 + 3][bcol] = pb[j].w;
            }
            __syncthreads();
        }
    }

    // ---- epilogue: store Y (no bias here; added in finish_kernel) ----
    #pragma unroll
    for (int i = 0; i < 8; ++i) {
        int row = m0 + ty + i;
        if (row >= N) continue;
        float o[8];
        #pragma unroll
        for (int j = 0; j < 4; ++j)
            unpack2(acc[i][j], o[2 * j], o[2 * j + 1]);
        float4* op = (float4*)(g_y + (size_t)row * D + n0 + tx);
        op[0] = make_float4(o[0], o[1], o[2], o[3]);
        op[1] = make_float4(o[4], o[5], o[6], o[7]);
    }
}

// ---------------------------------------------------------------------------
// Kernel 3: finish  out[i] = Y[i] + w(i,prev)*Y[prev] + w(i,next)*Y[next] + b
// (adj @ (X @ W^T) + b  ==  (adj @ X) @ W^T + b)
// ---------------------------------------------------------------------------
__global__ void finish_kernel(const float* __restrict__ bias,
                              float* __restrict__ out, int N)
{
    int i = blockIdx.x;
    if (i >= N) return;
    int t = threadIdx.x;   // 0..127

    const float4* y4 = (const float4*)g_y;
    float4 v = y4[(size_t)i * D4 + t];
    int p  = g_prev[i];
    int nx = g_next[i];
    if (p >= 0) {
        float w = g_wprev[i];
        float4 u = y4[(size_t)p * D4 + t];
        v.x += w * u.x; v.y += w * u.y; v.z += w * u.z; v.w += w * u.w;
    }
    if (nx >= 0) {
        float w = g_wprev[nx];
        float4 u = y4[(size_t)nx * D4 + t];
        v.x += w * u.x; v.y += w * u.y; v.z += w * u.z; v.w += w * u.w;
    }
    float4 b = ((const float4*)bias)[t];
    v.x += b.x; v.y += b.y; v.z += b.z; v.w += b.w;
    ((float4*)out)[(size_t)i * D4 + t] = v;
}

// ---------------------------------------------------------------------------
extern "C" void kernel_launch(void* const* d_in, const int* in_sizes, int n_in,
                              void* d_out, int out_size)
{
    const float* inputs  = (const float*)d_in[0];
    const int*   dia_len = (const int*)d_in[1];   // int32 or int64 (detected)
    const int*   qmask   = (const int*)d_in[2];   // int32 or int64 (detected)
    const float* Wm      = (const float*)d_in[3];
    const float* bias    = (const float*)d_in[4];
    float*       out     = (float*)d_out;

    int N  = in_sizes[0] / D;      // 6000
    int nd = in_sizes[1];
    if (nd > N) nd = N;

    prep_kernel<<<nd, 256>>>(inputs, dia_len, qmask, nd, N);

    dim3 grid((N + 127) / 128, D / 64);
    gemm_kernel<<<grid, 128>>>(inputs, Wm, N);

    finish_kernel<<<N, 128>>>(bias, out, N);
}

// round 6
// speedup vs baseline: 2.9696x; 1.7927x over previous
#include <cuda_runtime.h>
#include <cuda_bf16.h>
#include <math.h>
#include <cstdint>

#define MAXN    6144
#define D       512
#define D4      128
#define INV_PI  0.318309886183790671f

// ---------------- device scratch (allocation-free rule) ----------------
__device__ int   g_prev[MAXN];
__device__ int   g_next[MAXN];
__device__ float g_wprev[MAXN];
__device__ float g_y[MAXN * D];                       // Y = X @ W^T
// X split: [MAXN][1024 bf16] = (hi | lo), row stride 2048 B (zero-init tail rows)
__device__ unsigned char g_ahl[MAXN * 2048];
// W split: [512][1536 bf16] = (hi | lo | hi), row stride 3072 B
__device__ unsigned char g_bhl[512 * 3072];

__device__ __forceinline__ uint32_t smem_u32(const void* p) {
    uint32_t a;
    asm("{ .reg .u64 t; cvta.to.shared.u64 t, %1; cvt.u32.u64 %0, t; }"
        : "=r"(a) : "l"(p));
    return a;
}

#define LDM4(r, addr) \
    asm volatile("ldmatrix.sync.aligned.m8n8.x4.shared.b16 {%0,%1,%2,%3}, [%4];" \
        : "=r"((r)[0]), "=r"((r)[1]), "=r"((r)[2]), "=r"((r)[3]) : "r"(addr))

#define MMA16816(c, a, b0, b1) \
    asm volatile("mma.sync.aligned.m16n8k16.row.col.f32.bf16.bf16.f32 " \
        "{%0,%1,%2,%3}, {%4,%5,%6,%7}, {%8,%9}, {%0,%1,%2,%3};" \
        : "+f"((c)[0]), "+f"((c)[1]), "+f"((c)[2]), "+f"((c)[3]) \
        : "r"((a)[0]), "r"((a)[1]), "r"((a)[2]), "r"((a)[3]), "r"(b0), "r"(b1))

// ---------------------------------------------------------------------------
// Kernel 1: per-dialog chain building. One block per dialog.
// O(1) dtype detection; dia_len prefix via SMEM (no dependent global chain).
// ---------------------------------------------------------------------------
__global__ void prep1_kernel(const int* __restrict__ dl,
                             const int* __restrict__ q,
                             int n_dialogs, int N)
{
    __shared__ int s_dl[512];
    __shared__ int s_sp[512];
    __shared__ int s_q64;

    int d = blockIdx.x;
    if (d >= n_dialogs) return;
    int tid = threadIdx.x;

    if (tid == 0) s_q64 = 0;
    __syncthreads();
    // int64 layout read as int32 words: pair (lo,hi) of entry i sums to the
    // entry value in {0,1}; within any one-hot pair one entry is 0, so a
    // violation is guaranteed among the first two checks. Check 64 for slack.
    if (tid < 64 && tid < N) {
        if (q[2 * tid] + q[2 * tid + 1] != 1) atomicExch(&s_q64, 1);
    }
    int dstride = (dl[1] == 0) ? 2 : 1;     // lengths positive
    if (tid < n_dialogs && tid < 512) s_dl[tid] = dl[tid * dstride];
    __syncthreads();
    int qstride = s_q64 ? 4 : 2;

    int start = 0;
    for (int t = 0; t < d; ++t) start += s_dl[t];    // smem reads, cheap
    int len = s_dl[d];

    for (int t = tid; t < len; t += blockDim.x)
        s_sp[t] = (q[(size_t)(start + t) * qstride] == 1) ? 0 : 1;
    __syncthreads();

    if (tid == 0) {
        int last[2] = {-1, -1};
        for (int t = 0; t < len; ++t) {
            int i = start + t;
            int s = s_sp[t];
            g_next[i] = -1;
            if (last[s] >= 0) {
                g_prev[i]       = last[s];
                g_next[last[s]] = i;
            } else {
                g_prev[i] = -1;
            }
            last[s] = i;
        }
    }
}

// ---------------------------------------------------------------------------
// Kernel 2: edge weights, one warp per node (wide grid).
// ---------------------------------------------------------------------------
__global__ void wt_kernel(const float* __restrict__ inputs, int N)
{
    int i = blockIdx.x * 8 + (threadIdx.x >> 5);
    if (i >= N) return;
    int p = g_prev[i];
    if (p < 0) return;
    int lane = threadIdx.x & 31;

    const float4* a4 = (const float4*)(inputs + (size_t)i * D);
    const float4* b4 = (const float4*)(inputs + (size_t)p * D);
    float dot = 0.f, na = 0.f, nb = 0.f;
    #pragma unroll
    for (int j = lane; j < D4; j += 32) {
        float4 a = a4[j];
        float4 b = b4[j];
        dot += a.x * b.x + a.y * b.y + a.z * b.z + a.w * b.w;
        na  += a.x * a.x + a.y * a.y + a.z * a.z + a.w * a.w;
        nb  += b.x * b.x + b.y * b.y + b.z * b.z + b.w * b.w;
    }
    #pragma unroll
    for (int off = 16; off > 0; off >>= 1) {
        dot += __shfl_down_sync(0xffffffffu, dot, off);
        na  += __shfl_down_sync(0xffffffffu, na,  off);
        nb  += __shfl_down_sync(0xffffffffu, nb,  off);
    }
    if (lane == 0) {
        float denom = sqrtf(na) * sqrtf(nb);
        float c = (denom > 0.f) ? (dot / denom) : 0.f;
        c = fminf(1.f, fmaxf(-1.f, c));
        g_wprev[i] = 1.f - acosf(c) * INV_PI;
    }
}

// ---------------------------------------------------------------------------
// Kernel 3a: X -> bf16 (hi | lo)
// ---------------------------------------------------------------------------
__global__ void xsplit_kernel(const float* __restrict__ X, int N)
{
    int i = blockIdx.x;
    if (i >= N) return;
    int t = threadIdx.x;   // 0..127
    float4 v = ((const float4*)(X + (size_t)i * D))[t];
    float f[4] = {v.x, v.y, v.z, v.w};
    unsigned short hs[4], ls[4];
    #pragma unroll
    for (int j = 0; j < 4; ++j) {
        __nv_bfloat16 h = __float2bfloat16(f[j]);
        __nv_bfloat16 l = __float2bfloat16(f[j] - __bfloat162float(h));
        hs[j] = __bfloat16_as_ushort(h);
        ls[j] = __bfloat16_as_ushort(l);
    }
    uint2 hv = make_uint2((uint32_t)hs[0] | ((uint32_t)hs[1] << 16),
                          (uint32_t)hs[2] | ((uint32_t)hs[3] << 16));
    uint2 lv = make_uint2((uint32_t)ls[0] | ((uint32_t)ls[1] << 16),
                          (uint32_t)ls[2] | ((uint32_t)ls[3] << 16));
    unsigned char* row = g_ahl + (size_t)i * 2048;
    ((uint2*)row)[t]          = hv;
    ((uint2*)(row + 1024))[t] = lv;
}

// ---------------------------------------------------------------------------
// Kernel 3b: W -> bf16 (hi | lo | hi)
// ---------------------------------------------------------------------------
__global__ void wsplit_kernel(const float* __restrict__ Wm)
{
    int r = blockIdx.x;        // 0..511
    int t = threadIdx.x;       // 0..127
    float4 w = ((const float4*)(Wm + (size_t)r * D))[t];
    float f[4] = {w.x, w.y, w.z, w.w};
    unsigned short hs[4], ls[4];
    #pragma unroll
    for (int j = 0; j < 4; ++j) {
        __nv_bfloat16 h = __float2bfloat16(f[j]);
        __nv_bfloat16 l = __float2bfloat16(f[j] - __bfloat162float(h));
        hs[j] = __bfloat16_as_ushort(h);
        ls[j] = __bfloat16_as_ushort(l);
    }
    uint2 hv = make_uint2((uint32_t)hs[0] | ((uint32_t)hs[1] << 16),
                          (uint32_t)hs[2] | ((uint32_t)hs[3] << 16));
    uint2 lv = make_uint2((uint32_t)ls[0] | ((uint32_t)ls[1] << 16),
                          (uint32_t)ls[2] | ((uint32_t)ls[3] << 16));
    unsigned char* row = g_bhl + (size_t)r * 3072;
    ((uint2*)row)[t]          = hv;   // hi
    ((uint2*)(row + 1024))[t] = lv;   // lo
    ((uint2*)(row + 2048))[t] = hv;   // hi (pairs with A's lo section)
}

// ---------------------------------------------------------------------------
// Kernel 4: HMMA GEMM  Y[N,512] = sum_{K=1536} Acat x Bcat^T  (fp32 accum)
//   k in [0,512):    A hi  x W hi
//   k in [512,1024): A hi  x W lo
//   k in [1024,1536):A lo  x W hi
// Block tile 128x64, BK=32, 256 threads (8 warps, 4x2 grid of 32x32 warp
// tiles), mma.m16n8k16 bf16 via ldmatrix, double-buffered smem with 80B
// padded rows (conflict-free ldmatrix phases).
// ---------------------------------------------------------------------------
__global__ __launch_bounds__(256, 2)
void gemm_mma(int N)
{
    __shared__ __align__(16) unsigned char sA[2][128 * 80];
    __shared__ __align__(16) unsigned char sB[2][64 * 80];

    int t = threadIdx.x;
    int m0 = blockIdx.x * 128;
    int n0 = blockIdx.y * 64;
    int lane = t & 31, w = t >> 5;
    int wm = w >> 1, wn = w & 1;

    // ---- global staging mapping (uint4 chunks; rows padded by g_ahl zeros) ----
    int sr = t >> 2, sc = t & 3;       // row 0..63, 16B chunk 0..3
    const unsigned char* gA0 = g_ahl + (size_t)(m0 + sr)      * 2048 + sc * 16;
    const unsigned char* gA1 = g_ahl + (size_t)(m0 + sr + 64) * 2048 + sc * 16;
    const unsigned char* gB  = g_bhl + (size_t)(n0 + sr)      * 3072 + sc * 16;

    uint32_t sa[2] = { smem_u32(sA[0]), smem_u32(sA[1]) };
    uint32_t sb[2] = { smem_u32(sB[0]), smem_u32(sB[1]) };
    uint32_t stA0 = sr * 80 + sc * 16;
    uint32_t stA1 = (sr + 64) * 80 + sc * 16;
    uint32_t stB  = sr * 80 + sc * 16;

    // ---- ldmatrix lane bases ----
    uint32_t a_ld = (uint32_t)(wm * 32 + (lane & 15)) * 80 + ((lane >> 4) * 16);
    uint32_t b_ld = (uint32_t)(wn * 32 + (lane & 15)) * 80 + ((lane >> 4) * 16);

    float acc[2][4][4];
    #pragma unroll
    for (int i = 0; i < 2; ++i)
        #pragma unroll
        for (int j = 0; j < 4; ++j)
            #pragma unroll
            for (int r = 0; r < 4; ++r) acc[i][j][r] = 0.f;

    // preload k-chunk 0 into buffer 0
    uint4 va0 = *(const uint4*)gA0;
    uint4 va1 = *(const uint4*)gA1;
    uint4 vb  = *(const uint4*)gB;
    *(uint4*)(sA[0] + stA0) = va0;
    *(uint4*)(sA[0] + stA1) = va1;
    *(uint4*)(sB[0] + stB)  = vb;
    __syncthreads();

    #pragma unroll 1
    for (int it = 0; it < 48; ++it) {
        int buf = it & 1;
        if (it < 47) {
            int k = (it + 1) * 32;
            int aoff = (k >= 512 ? k - 512 : k) * 2;
            int boff = k * 2;
            va0 = *(const uint4*)(gA0 + aoff);
            va1 = *(const uint4*)(gA1 + aoff);
            vb  = *(const uint4*)(gB + boff);
        }

        uint32_t ab = sa[buf] + a_ld;
        uint32_t bb = sb[buf] + b_ld;
        #pragma unroll
        for (int kk = 0; kk < 2; ++kk) {
            uint32_t A0[4], A1[4], B0[4], B1[4];
            LDM4(A0, ab + kk * 32);
            LDM4(A1, ab + 16 * 80 + kk * 32);
            LDM4(B0, bb + kk * 32);
            LDM4(B1, bb + 16 * 80 + kk * 32);
            MMA16816(acc[0][0], A0, B0[0], B0[2]);
            MMA16816(acc[0][1], A0, B0[1], B0[3]);
            MMA16816(acc[0][2], A0, B1[0], B1[2]);
            MMA16816(acc[0][3], A0, B1[1], B1[3]);
            MMA16816(acc[1][0], A1, B0[0], B0[2]);
            MMA16816(acc[1][1], A1, B0[1], B0[3]);
            MMA16816(acc[1][2], A1, B1[0], B1[2]);
            MMA16816(acc[1][3], A1, B1[1], B1[3]);
        }

        if (it < 47) {
            int wb = buf ^ 1;       // last read two syncs ago; safe to fill
            *(uint4*)(sA[wb] + stA0) = va0;
            *(uint4*)(sA[wb] + stA1) = va1;
            *(uint4*)(sB[wb] + stB)  = vb;
            __syncthreads();
        }
    }

    // ---- epilogue: store Y ----
    int r0 = m0 + wm * 32 + (lane >> 2);
    int cb = n0 + wn * 32 + (lane & 3) * 2;
    #pragma unroll
    for (int mi = 0; mi < 2; ++mi) {
        int row = r0 + mi * 16;
        #pragma unroll
        for (int nj = 0; nj < 4; ++nj) {
            int col = cb + nj * 8;
            if (row < N)
                *(float2*)(g_y + (size_t)row * D + col) =
                    make_float2(acc[mi][nj][0], acc[mi][nj][1]);
            if (row + 8 < N)
                *(float2*)(g_y + (size_t)(row + 8) * D + col) =
                    make_float2(acc[mi][nj][2], acc[mi][nj][3]);
        }
    }
}

// ---------------------------------------------------------------------------
// Kernel 5: finish  out[i] = Y[i] + w(i,prev)*Y[prev] + w(i,next)*Y[next] + b
// ---------------------------------------------------------------------------
__global__ void finish_kernel(const float* __restrict__ bias,
                              float* __restrict__ out, int N)
{
    int i = blockIdx.x;
    if (i >= N) return;
    int t = threadIdx.x;

    const float4* y4 = (const float4*)g_y;
    float4 v = y4[(size_t)i * D4 + t];
    int p  = g_prev[i];
    int nx = g_next[i];
    if (p >= 0) {
        float w = g_wprev[i];
        float4 u = y4[(size_t)p * D4 + t];
        v.x += w * u.x; v.y += w * u.y; v.z += w * u.z; v.w += w * u.w;
    }
    if (nx >= 0) {
        float w = g_wprev[nx];
        float4 u = y4[(size_t)nx * D4 + t];
        v.x += w * u.x; v.y += w * u.y; v.z += w * u.z; v.w += w * u.w;
    }
    float4 b = ((const float4*)bias)[t];
    v.x += b.x; v.y += b.y; v.z += b.z; v.w += b.w;
    ((float4*)out)[(size_t)i * D4 + t] = v;
}

// ---------------------------------------------------------------------------
extern "C" void kernel_launch(void* const* d_in, const int* in_sizes, int n_in,
                              void* d_out, int out_size)
{
    const float* inputs  = (const float*)d_in[0];
    const int*   dia_len = (const int*)d_in[1];
    const int*   qmask   = (const int*)d_in[2];
    const float* Wm      = (const float*)d_in[3];
    const float* bias    = (const float*)d_in[4];
    float*       out     = (float*)d_out;

    int N  = in_sizes[0] / D;      // 6000
    int nd = in_sizes[1];
    if (nd > N) nd = N;

    prep1_kernel<<<nd, 128>>>(dia_len, qmask, nd, N);
    wt_kernel<<<(N + 7) / 8, 256>>>(inputs, N);
    xsplit_kernel<<<N, 128>>>(inputs, N);
    wsplit_kernel<<<512, 128>>>(Wm);

    dim3 grid((N + 127) / 128, D / 64);
    gemm_mma<<<grid, 256>>>(N);

    finish_kernel<<<N, 128>>>(bias, out, N);
}